// round 3
// baseline (speedup 1.0000x reference)
#include <cuda_runtime.h>
#include <math.h>

#define BATCH 2
#define SEQ   2048
#define DM    1024
#define NH    16
#define HD    64
#define UTOP  38
#define QB    8
#define MAXK  256

// Scratch (allocation-free rule: __device__ globals)
__device__ float g_Q[BATCH*SEQ*DM];
__device__ float g_K[BATCH*SEQ*DM];
__device__ float g_V[BATCH*SEQ*DM];
__device__ float g_C[BATCH*SEQ*DM];

// ---------------------------------------------------------------------------
// Fast fp32 SGEMM: Cout[M,N] = A[M,K] @ W[N,K]^T + bias[N]
// 128x128 block tile, BK=16, 256 threads, 8x8 register tile.
// Used for V projection and output projection (precision non-critical).
// ---------------------------------------------------------------------------
__global__ __launch_bounds__(256) void sgemm_bias(
    const float* __restrict__ A, const float* __restrict__ W,
    const float* __restrict__ bias, float* __restrict__ Cout,
    int M, int N, int Kdim)
{
    __shared__ float As[16][128];
    __shared__ float Ws[16][128];
    int t  = threadIdx.x;
    int m0 = blockIdx.y * 128;
    int n0 = blockIdx.x * 128;
    int tm = t >> 4, tn = t & 15;
    int lr = t >> 2;          // 0..63
    int lc = (t & 3) << 2;    // 0,4,8,12

    float acc[8][8];
    #pragma unroll
    for (int i = 0; i < 8; i++)
        #pragma unroll
        for (int j = 0; j < 8; j++) acc[i][j] = 0.f;

    for (int k0 = 0; k0 < Kdim; k0 += 16) {
        float4 a0 = *(const float4*)(A + (size_t)(m0+lr   )*Kdim + k0 + lc);
        float4 a1 = *(const float4*)(A + (size_t)(m0+lr+64)*Kdim + k0 + lc);
        float4 w0 = *(const float4*)(W + (size_t)(n0+lr   )*Kdim + k0 + lc);
        float4 w1 = *(const float4*)(W + (size_t)(n0+lr+64)*Kdim + k0 + lc);
        __syncthreads();
        As[lc+0][lr]    = a0.x; As[lc+1][lr]    = a0.y; As[lc+2][lr]    = a0.z; As[lc+3][lr]    = a0.w;
        As[lc+0][lr+64] = a1.x; As[lc+1][lr+64] = a1.y; As[lc+2][lr+64] = a1.z; As[lc+3][lr+64] = a1.w;
        Ws[lc+0][lr]    = w0.x; Ws[lc+1][lr]    = w0.y; Ws[lc+2][lr]    = w0.z; Ws[lc+3][lr]    = w0.w;
        Ws[lc+0][lr+64] = w1.x; Ws[lc+1][lr+64] = w1.y; Ws[lc+2][lr+64] = w1.z; Ws[lc+3][lr+64] = w1.w;
        __syncthreads();
        #pragma unroll
        for (int kk = 0; kk < 16; kk++) {
            float a[8], bb[8];
            *(float4*)(a)    = *(const float4*)&As[kk][tm*8];
            *(float4*)(a+4)  = *(const float4*)&As[kk][tm*8+4];
            *(float4*)(bb)   = *(const float4*)&Ws[kk][tn*8];
            *(float4*)(bb+4) = *(const float4*)&Ws[kk][tn*8+4];
            #pragma unroll
            for (int i = 0; i < 8; i++)
                #pragma unroll
                for (int j = 0; j < 8; j++)
                    acc[i][j] = fmaf(a[i], bb[j], acc[i][j]);
        }
    }
    #pragma unroll
    for (int i = 0; i < 8; i++) {
        int m = m0 + tm*8 + i;
        #pragma unroll
        for (int j = 0; j < 8; j += 4) {
            int n = n0 + tn*8 + j;
            float4 r;
            r.x = acc[i][j]   + bias[n];
            r.y = acc[i][j+1] + bias[n+1];
            r.z = acc[i][j+2] + bias[n+2];
            r.w = acc[i][j+3] + bias[n+3];
            *(float4*)(Cout + (size_t)m*N + n) = r;
        }
    }
}

// ---------------------------------------------------------------------------
// High-accuracy SGEMM (double-float / compensated accumulation).
// Used for Q and K projections: their values feed the top-k selection, where
// ~6e-7 score error flips borderline selections vs the fp32 reference.
// Error-free transform per term: prod + FMA residual + fast two-sum carry.
// 64x64 block tile, BK=16, 256 threads, 4x4 register tile (hi+lo accums).
// ---------------------------------------------------------------------------
__global__ __launch_bounds__(256) void sgemm_bias_df(
    const float* __restrict__ A, const float* __restrict__ W,
    const float* __restrict__ bias, float* __restrict__ Cout,
    int M, int N, int Kdim)
{
    __shared__ float As[16][64];
    __shared__ float Ws[16][64];
    int t  = threadIdx.x;
    int m0 = blockIdx.y * 64;
    int n0 = blockIdx.x * 64;
    int tm = t >> 4, tn = t & 15;
    int lr = t >> 2;          // 0..63
    int lc = (t & 3) << 2;    // 0,4,8,12

    float hi[4][4], lo[4][4];
    #pragma unroll
    for (int i = 0; i < 4; i++)
        #pragma unroll
        for (int j = 0; j < 4; j++) { hi[i][j] = 0.f; lo[i][j] = 0.f; }

    for (int k0 = 0; k0 < Kdim; k0 += 16) {
        float4 a0 = *(const float4*)(A + (size_t)(m0+lr)*Kdim + k0 + lc);
        float4 w0 = *(const float4*)(W + (size_t)(n0+lr)*Kdim + k0 + lc);
        __syncthreads();
        As[lc+0][lr] = a0.x; As[lc+1][lr] = a0.y; As[lc+2][lr] = a0.z; As[lc+3][lr] = a0.w;
        Ws[lc+0][lr] = w0.x; Ws[lc+1][lr] = w0.y; Ws[lc+2][lr] = w0.z; Ws[lc+3][lr] = w0.w;
        __syncthreads();
        #pragma unroll
        for (int kk = 0; kk < 16; kk++) {
            float a[4], bb[4];
            *(float4*)(a)  = *(const float4*)&As[kk][tm*4];
            *(float4*)(bb) = *(const float4*)&Ws[kk][tn*4];
            #pragma unroll
            for (int i = 0; i < 4; i++)
                #pragma unroll
                for (int j = 0; j < 4; j++) {
                    float p  = a[i] * bb[j];
                    float pe = fmaf(a[i], bb[j], -p);      // exact product residual
                    float s  = hi[i][j] + p;
                    float e  = (hi[i][j] - s) + p;         // fast two-sum residual
                    hi[i][j] = s;
                    lo[i][j] += (e + pe);
                }
        }
    }
    #pragma unroll
    for (int i = 0; i < 4; i++) {
        int m = m0 + tm*4 + i;
        int n = n0 + tn*4;
        float4 r;
        r.x = (hi[i][0] + lo[i][0]) + bias[n+0];
        r.y = (hi[i][1] + lo[i][1]) + bias[n+1];
        r.z = (hi[i][2] + lo[i][2]) + bias[n+2];
        r.w = (hi[i][3] + lo[i][3]) + bias[n+3];
        *(float4*)(Cout + (size_t)m*N + n) = r;
    }
}

// ---------------------------------------------------------------------------
// ProbSparse attention. One warp per query row; block = 8 query rows of one
// (b,h). Exact top-U threshold via binary search on order-preserving uint map.
// ---------------------------------------------------------------------------
__device__ __forceinline__ unsigned f2u(float f) {
    unsigned u = __float_as_uint(f);
    return (u & 0x80000000u) ? ~u : (u | 0x80000000u);
}

__global__ __launch_bounds__(256) void attn_kernel(
    const float* __restrict__ Q, const float* __restrict__ K,
    const float* __restrict__ V, float* __restrict__ C)
{
    extern __shared__ float smem[];
    float* sc   = smem;                            // [QB][SEQ]
    int*   sidx = (int*)(smem + QB*SEQ);           // [QB][MAXK]
    float* sp   = (float*)(sidx + QB*MAXK);        // [QB][MAXK]

    int t    = threadIdx.x;
    int qq   = t >> 5;
    int lane = t & 31;
    int bh   = blockIdx.y;
    int b    = bh / NH, h = bh % NH;
    int q    = blockIdx.x * QB + qq;

    const float* Kb   = K + (size_t)b*SEQ*DM + h*HD;
    const float* Vb   = V + (size_t)b*SEQ*DM + h*HD;
    const float* qrow = Q + ((size_t)b*SEQ + q)*DM + h*HD;

    float qreg[HD];
    #pragma unroll
    for (int d = 0; d < HD; d += 4) {
        float4 v = *(const float4*)(qrow + d);
        qreg[d] = v.x; qreg[d+1] = v.y; qreg[d+2] = v.z; qreg[d+3] = v.w;
    }

    float* row = sc + qq*SEQ;
    float mymax = -INFINITY;
    // Pass 1: scores = (q . K_k) / 8  — two split accumulators to halve
    // sequential-accumulation rounding error.
    for (int i = 0; i < SEQ/32; i++) {
        int k = lane + 32*i;
        const float* kr = Kb + (size_t)k*DM;
        float accA = 0.f, accB = 0.f;
        #pragma unroll
        for (int d = 0; d < HD/2; d += 4) {
            float4 kv = *(const float4*)(kr + d);
            accA = fmaf(kv.x, qreg[d],   accA);
            accA = fmaf(kv.y, qreg[d+1], accA);
            accA = fmaf(kv.z, qreg[d+2], accA);
            accA = fmaf(kv.w, qreg[d+3], accA);
            float4 kw = *(const float4*)(kr + d + HD/2);
            accB = fmaf(kw.x, qreg[d+HD/2],   accB);
            accB = fmaf(kw.y, qreg[d+1+HD/2], accB);
            accB = fmaf(kw.z, qreg[d+2+HD/2], accB);
            accB = fmaf(kw.w, qreg[d+3+HD/2], accB);
        }
        float acc = (accA + accB) * 0.125f;
        row[k] = acc;
        mymax = fmaxf(mymax, acc);
    }
    #pragma unroll
    for (int o = 16; o; o >>= 1)
        mymax = fmaxf(mymax, __shfl_xor_sync(0xffffffffu, mymax, o));

    // Exact U-th largest via binary search over monotonic uint mapping.
    unsigned lo = 0u, hi = 0xFFFFFFFFu;
    while (lo < hi) {
        unsigned d  = hi - lo;
        unsigned mid = lo + (d >> 1) + (d & 1u);   // ceil midpoint, lo < mid <= hi
        int c = 0;
        for (int i = 0; i < SEQ/32; i++)
            c += (f2u(row[lane + 32*i]) >= mid) ? 1 : 0;
        #pragma unroll
        for (int o = 16; o; o >>= 1) c += __shfl_xor_sync(0xffffffffu, c, o);
        if (c >= UTOP) lo = mid; else hi = mid - 1;
    }
    const unsigned uth = lo;   // keep scores with f2u(s) >= uth  (== s >= thresh)

    // Softmax over kept entries + compaction
    float sum = 0.f;
    int cnt = 0;
    for (int i = 0; i < SEQ/32; i++) {
        int k = lane + 32*i;
        float s = row[k];
        bool keep = (f2u(s) >= uth);
        float p = keep ? __expf(s - mymax) : 0.f;
        sum += p;
        unsigned msk = __ballot_sync(0xffffffffu, keep);
        if (keep) {
            int pos = cnt + __popc(msk & ((1u << lane) - 1u));
            if (pos < MAXK) { sidx[qq*MAXK + pos] = k; sp[qq*MAXK + pos] = p; }
        }
        cnt += __popc(msk);
    }
    #pragma unroll
    for (int o = 16; o; o >>= 1) sum += __shfl_xor_sync(0xffffffffu, sum, o);
    float inv = 1.f / sum;
    __syncwarp();

    // Sparse context accumulation: lane owns dims (lane, lane+32)
    float acc0 = 0.f, acc1 = 0.f;
    if (cnt <= MAXK) {
        for (int j = 0; j < cnt; j++) {
            int   k = sidx[qq*MAXK + j];
            float p = sp[qq*MAXK + j];
            const float* vr = Vb + (size_t)k*DM;
            acc0 = fmaf(p, vr[lane],      acc0);
            acc1 = fmaf(p, vr[lane + 32], acc1);
        }
    } else {
        // tie-overflow fallback (rare): dense walk
        for (int k = 0; k < SEQ; k++) {
            float s = row[k];
            if (f2u(s) >= uth) {
                float p = __expf(s - mymax);
                const float* vr = Vb + (size_t)k*DM;
                acc0 = fmaf(p, vr[lane],      acc0);
                acc1 = fmaf(p, vr[lane + 32], acc1);
            }
        }
    }
    float* out = C + ((size_t)b*SEQ + q)*DM + h*HD;
    out[lane]      = acc0 * inv;
    out[lane + 32] = acc1 * inv;
}

// ---------------------------------------------------------------------------
extern "C" void kernel_launch(void* const* d_in, const int* in_sizes, int n_in,
                              void* d_out, int out_size)
{
    const float* x  = (const float*)d_in[0];
    const float* Wq = (const float*)d_in[1];
    const float* bq = (const float*)d_in[2];
    const float* Wk = (const float*)d_in[3];
    const float* bk = (const float*)d_in[4];
    const float* Wv = (const float*)d_in[5];
    const float* bv = (const float*)d_in[6];
    const float* Wo = (const float*)d_in[7];
    const float* bo = (const float*)d_in[8];
    float* out = (float*)d_out;

    float *Qp, *Kp, *Vp, *Cp;
    cudaGetSymbolAddress((void**)&Qp, g_Q);
    cudaGetSymbolAddress((void**)&Kp, g_K);
    cudaGetSymbolAddress((void**)&Vp, g_V);
    cudaGetSymbolAddress((void**)&Cp, g_C);

    const int M = BATCH * SEQ;
    dim3 gg(DM/128, M/128);     // (8, 32)  fast path
    dim3 gd(DM/64,  M/64);      // (16, 64) df path
    sgemm_bias_df<<<gd, 256>>>(x, Wq, bq, Qp, M, DM, DM);
    sgemm_bias_df<<<gd, 256>>>(x, Wk, bk, Kp, M, DM, DM);
    sgemm_bias<<<gg, 256>>>(x, Wv, bv, Vp, M, DM, DM);

    size_t smem = (size_t)QB*SEQ*4 + (size_t)QB*MAXK*4*2;  // 81920 B
    cudaFuncSetAttribute(attn_kernel, cudaFuncAttributeMaxDynamicSharedMemorySize, (int)smem);
    attn_kernel<<<dim3(SEQ/QB, BATCH*NH), 256, smem>>>(Qp, Kp, Vp, Cp);

    sgemm_bias<<<gg, 256>>>(Cp, Wo, bo, out, M, DM, DM);
}

// round 6
// speedup vs baseline: 1.1935x; 1.1935x over previous
#include <cuda_runtime.h>
#include <math.h>

#define BATCH 2
#define SEQ   2048
#define DM    1024
#define NH    16
#define HD    64
#define UTOP  38
#define QB    8
#define MAXK  256

// Scratch (allocation-free rule: __device__ globals)
__device__ float g_Q[BATCH*SEQ*DM];
__device__ float g_K[BATCH*SEQ*DM];
__device__ float g_V[BATCH*SEQ*DM];
__device__ float g_C[BATCH*SEQ*DM];

// ---------------------------------------------------------------------------
// Fast fp32 SGEMM: Cout[M,N] = A[M,K] @ W[N,K]^T + bias[N]
// 128x128 block tile, BK=16, 256 threads, 8x8 register tile.
// Used for V projection and output projection (precision non-critical).
// ---------------------------------------------------------------------------
__global__ __launch_bounds__(256) void sgemm_bias(
    const float* __restrict__ A, const float* __restrict__ W,
    const float* __restrict__ bias, float* __restrict__ Cout,
    int M, int N, int Kdim)
{
    __shared__ float As[16][128];
    __shared__ float Ws[16][128];
    int t  = threadIdx.x;
    int m0 = blockIdx.y * 128;
    int n0 = blockIdx.x * 128;
    int tm = t >> 4, tn = t & 15;
    int lr = t >> 2;          // 0..63
    int lc = (t & 3) << 2;    // 0,4,8,12

    float acc[8][8];
    #pragma unroll
    for (int i = 0; i < 8; i++)
        #pragma unroll
        for (int j = 0; j < 8; j++) acc[i][j] = 0.f;

    for (int k0 = 0; k0 < Kdim; k0 += 16) {
        float4 a0 = *(const float4*)(A + (size_t)(m0+lr   )*Kdim + k0 + lc);
        float4 a1 = *(const float4*)(A + (size_t)(m0+lr+64)*Kdim + k0 + lc);
        float4 w0 = *(const float4*)(W + (size_t)(n0+lr   )*Kdim + k0 + lc);
        float4 w1 = *(const float4*)(W + (size_t)(n0+lr+64)*Kdim + k0 + lc);
        __syncthreads();
        As[lc+0][lr]    = a0.x; As[lc+1][lr]    = a0.y; As[lc+2][lr]    = a0.z; As[lc+3][lr]    = a0.w;
        As[lc+0][lr+64] = a1.x; As[lc+1][lr+64] = a1.y; As[lc+2][lr+64] = a1.z; As[lc+3][lr+64] = a1.w;
        Ws[lc+0][lr]    = w0.x; Ws[lc+1][lr]    = w0.y; Ws[lc+2][lr]    = w0.z; Ws[lc+3][lr]    = w0.w;
        Ws[lc+0][lr+64] = w1.x; Ws[lc+1][lr+64] = w1.y; Ws[lc+2][lr+64] = w1.z; Ws[lc+3][lr+64] = w1.w;
        __syncthreads();
        #pragma unroll
        for (int kk = 0; kk < 16; kk++) {
            float a[8], bb[8];
            *(float4*)(a)    = *(const float4*)&As[kk][tm*8];
            *(float4*)(a+4)  = *(const float4*)&As[kk][tm*8+4];
            *(float4*)(bb)   = *(const float4*)&Ws[kk][tn*8];
            *(float4*)(bb+4) = *(const float4*)&Ws[kk][tn*8+4];
            #pragma unroll
            for (int i = 0; i < 8; i++)
                #pragma unroll
                for (int j = 0; j < 8; j++)
                    acc[i][j] = fmaf(a[i], bb[j], acc[i][j]);
        }
    }
    #pragma unroll
    for (int i = 0; i < 8; i++) {
        int m = m0 + tm*8 + i;
        #pragma unroll
        for (int j = 0; j < 8; j += 4) {
            int n = n0 + tn*8 + j;
            float4 r;
            r.x = acc[i][j]   + bias[n];
            r.y = acc[i][j+1] + bias[n+1];
            r.z = acc[i][j+2] + bias[n+2];
            r.w = acc[i][j+3] + bias[n+3];
            *(float4*)(Cout + (size_t)m*N + n) = r;
        }
    }
}

// ---------------------------------------------------------------------------
// High-accuracy two-level SGEMM for Q and K projections.
// Inner: plain FMA over one BK=16 tile into tmp (partial sums stay small, so
// rounding per tile is ~1e-8). Outer: Kahan-compensated add of each tile
// partial into the master accumulator (master chain error ~0).
// Resulting Q/K entry noise ~6e-8 — well below the reference's own fp32
// rounding (~1.5e-7), so top-k selection matches round-3 df accuracy at
// ~1.3x the cost of the plain fast GEMM.
// 128x64 block tile, BK=16, 256 threads, 8x4 register tile.
// ---------------------------------------------------------------------------
__global__ __launch_bounds__(256) void sgemm_bias_2lvl(
    const float* __restrict__ A, const float* __restrict__ W,
    const float* __restrict__ bias, float* __restrict__ Cout,
    int M, int N, int Kdim)
{
    __shared__ float As[16][128];
    __shared__ float Ws[16][64];
    int t  = threadIdx.x;
    int m0 = blockIdx.y * 128;
    int n0 = blockIdx.x * 64;
    int tm = t >> 4, tn = t & 15;
    int lr = t >> 2;          // 0..63
    int lc = (t & 3) << 2;    // 0,4,8,12

    float acc[8][4], cmp[8][4];
    #pragma unroll
    for (int i = 0; i < 8; i++)
        #pragma unroll
        for (int j = 0; j < 4; j++) { acc[i][j] = 0.f; cmp[i][j] = 0.f; }

    for (int k0 = 0; k0 < Kdim; k0 += 16) {
        float4 a0 = *(const float4*)(A + (size_t)(m0+lr   )*Kdim + k0 + lc);
        float4 a1 = *(const float4*)(A + (size_t)(m0+lr+64)*Kdim + k0 + lc);
        float4 w0 = *(const float4*)(W + (size_t)(n0+lr   )*Kdim + k0 + lc);
        __syncthreads();
        As[lc+0][lr]    = a0.x; As[lc+1][lr]    = a0.y; As[lc+2][lr]    = a0.z; As[lc+3][lr]    = a0.w;
        As[lc+0][lr+64] = a1.x; As[lc+1][lr+64] = a1.y; As[lc+2][lr+64] = a1.z; As[lc+3][lr+64] = a1.w;
        Ws[lc+0][lr]    = w0.x; Ws[lc+1][lr]    = w0.y; Ws[lc+2][lr]    = w0.z; Ws[lc+3][lr]    = w0.w;
        __syncthreads();

        float tmp[8][4];
        #pragma unroll
        for (int i = 0; i < 8; i++)
            #pragma unroll
            for (int j = 0; j < 4; j++) tmp[i][j] = 0.f;

        #pragma unroll
        for (int kk = 0; kk < 16; kk++) {
            float a[8], bb[4];
            *(float4*)(a)    = *(const float4*)&As[kk][tm*8];
            *(float4*)(a+4)  = *(const float4*)&As[kk][tm*8+4];
            *(float4*)(bb)   = *(const float4*)&Ws[kk][tn*4];
            #pragma unroll
            for (int i = 0; i < 8; i++)
                #pragma unroll
                for (int j = 0; j < 4; j++)
                    tmp[i][j] = fmaf(a[i], bb[j], tmp[i][j]);
        }

        // Kahan add of tile partial into master accumulator
        #pragma unroll
        for (int i = 0; i < 8; i++)
            #pragma unroll
            for (int j = 0; j < 4; j++) {
                float y = tmp[i][j] - cmp[i][j];
                float s = acc[i][j] + y;
                cmp[i][j] = (s - acc[i][j]) - y;
                acc[i][j] = s;
            }
    }
    #pragma unroll
    for (int i = 0; i < 8; i++) {
        int m = m0 + tm*8 + i;
        int n = n0 + tn*4;
        float4 r;
        r.x = acc[i][0] + bias[n+0];
        r.y = acc[i][1] + bias[n+1];
        r.z = acc[i][2] + bias[n+2];
        r.w = acc[i][3] + bias[n+3];
        *(float4*)(Cout + (size_t)m*N + n) = r;
    }
}

// ---------------------------------------------------------------------------
// ProbSparse attention. One warp per query row; block = 8 query rows of one
// (b,h). Exact top-U threshold via binary search on order-preserving uint map.
// (Identical to the round-3 passing version.)
// ---------------------------------------------------------------------------
__device__ __forceinline__ unsigned f2u(float f) {
    unsigned u = __float_as_uint(f);
    return (u & 0x80000000u) ? ~u : (u | 0x80000000u);
}

__global__ __launch_bounds__(256) void attn_kernel(
    const float* __restrict__ Q, const float* __restrict__ K,
    const float* __restrict__ V, float* __restrict__ C)
{
    extern __shared__ float smem[];
    float* sc   = smem;                            // [QB][SEQ]
    int*   sidx = (int*)(smem + QB*SEQ);           // [QB][MAXK]
    float* sp   = (float*)(sidx + QB*MAXK);        // [QB][MAXK]

    int t    = threadIdx.x;
    int qq   = t >> 5;
    int lane = t & 31;
    int bh   = blockIdx.y;
    int b    = bh / NH, h = bh % NH;
    int q    = blockIdx.x * QB + qq;

    const float* Kb   = K + (size_t)b*SEQ*DM + h*HD;
    const float* Vb   = V + (size_t)b*SEQ*DM + h*HD;
    const float* qrow = Q + ((size_t)b*SEQ + q)*DM + h*HD;

    float qreg[HD];
    #pragma unroll
    for (int d = 0; d < HD; d += 4) {
        float4 v = *(const float4*)(qrow + d);
        qreg[d] = v.x; qreg[d+1] = v.y; qreg[d+2] = v.z; qreg[d+3] = v.w;
    }

    float* row = sc + qq*SEQ;
    float mymax = -INFINITY;
    // Pass 1: scores = (q . K_k) / 8  — two split accumulators to halve
    // sequential-accumulation rounding error.
    for (int i = 0; i < SEQ/32; i++) {
        int k = lane + 32*i;
        const float* kr = Kb + (size_t)k*DM;
        float accA = 0.f, accB = 0.f;
        #pragma unroll
        for (int d = 0; d < HD/2; d += 4) {
            float4 kv = *(const float4*)(kr + d);
            accA = fmaf(kv.x, qreg[d],   accA);
            accA = fmaf(kv.y, qreg[d+1], accA);
            accA = fmaf(kv.z, qreg[d+2], accA);
            accA = fmaf(kv.w, qreg[d+3], accA);
            float4 kw = *(const float4*)(kr + d + HD/2);
            accB = fmaf(kw.x, qreg[d+HD/2],   accB);
            accB = fmaf(kw.y, qreg[d+1+HD/2], accB);
            accB = fmaf(kw.z, qreg[d+2+HD/2], accB);
            accB = fmaf(kw.w, qreg[d+3+HD/2], accB);
        }
        float acc = (accA + accB) * 0.125f;
        row[k] = acc;
        mymax = fmaxf(mymax, acc);
    }
    #pragma unroll
    for (int o = 16; o; o >>= 1)
        mymax = fmaxf(mymax, __shfl_xor_sync(0xffffffffu, mymax, o));

    // Exact U-th largest via binary search over monotonic uint mapping.
    unsigned lo = 0u, hi = 0xFFFFFFFFu;
    while (lo < hi) {
        unsigned d  = hi - lo;
        unsigned mid = lo + (d >> 1) + (d & 1u);   // ceil midpoint, lo < mid <= hi
        int c = 0;
        for (int i = 0; i < SEQ/32; i++)
            c += (f2u(row[lane + 32*i]) >= mid) ? 1 : 0;
        #pragma unroll
        for (int o = 16; o; o >>= 1) c += __shfl_xor_sync(0xffffffffu, c, o);
        if (c >= UTOP) lo = mid; else hi = mid - 1;
    }
    const unsigned uth = lo;   // keep scores with f2u(s) >= uth  (== s >= thresh)

    // Softmax over kept entries + compaction
    float sum = 0.f;
    int cnt = 0;
    for (int i = 0; i < SEQ/32; i++) {
        int k = lane + 32*i;
        float s = row[k];
        bool keep = (f2u(s) >= uth);
        float p = keep ? __expf(s - mymax) : 0.f;
        sum += p;
        unsigned msk = __ballot_sync(0xffffffffu, keep);
        if (keep) {
            int pos = cnt + __popc(msk & ((1u << lane) - 1u));
            if (pos < MAXK) { sidx[qq*MAXK + pos] = k; sp[qq*MAXK + pos] = p; }
        }
        cnt += __popc(msk);
    }
    #pragma unroll
    for (int o = 16; o; o >>= 1) sum += __shfl_xor_sync(0xffffffffu, sum, o);
    float inv = 1.f / sum;
    __syncwarp();

    // Sparse context accumulation: lane owns dims (lane, lane+32)
    float acc0 = 0.f, acc1 = 0.f;
    if (cnt <= MAXK) {
        for (int j = 0; j < cnt; j++) {
            int   k = sidx[qq*MAXK + j];
            float p = sp[qq*MAXK + j];
            const float* vr = Vb + (size_t)k*DM;
            acc0 = fmaf(p, vr[lane],      acc0);
            acc1 = fmaf(p, vr[lane + 32], acc1);
        }
    } else {
        // tie-overflow fallback (rare): dense walk
        for (int k = 0; k < SEQ; k++) {
            float s = row[k];
            if (f2u(s) >= uth) {
                float p = __expf(s - mymax);
                const float* vr = Vb + (size_t)k*DM;
                acc0 = fmaf(p, vr[lane],      acc0);
                acc1 = fmaf(p, vr[lane + 32], acc1);
            }
        }
    }
    float* out = C + ((size_t)b*SEQ + q)*DM + h*HD;
    out[lane]      = acc0 * inv;
    out[lane + 32] = acc1 * inv;
}

// ---------------------------------------------------------------------------
extern "C" void kernel_launch(void* const* d_in, const int* in_sizes, int n_in,
                              void* d_out, int out_size)
{
    const float* x  = (const float*)d_in[0];
    const float* Wq = (const float*)d_in[1];
    const float* bq = (const float*)d_in[2];
    const float* Wk = (const float*)d_in[3];
    const float* bk = (const float*)d_in[4];
    const float* Wv = (const float*)d_in[5];
    const float* bv = (const float*)d_in[6];
    const float* Wo = (const float*)d_in[7];
    const float* bo = (const float*)d_in[8];
    float* out = (float*)d_out;

    float *Qp, *Kp, *Vp, *Cp;
    cudaGetSymbolAddress((void**)&Qp, g_Q);
    cudaGetSymbolAddress((void**)&Kp, g_K);
    cudaGetSymbolAddress((void**)&Vp, g_V);
    cudaGetSymbolAddress((void**)&Cp, g_C);

    const int M = BATCH * SEQ;
    dim3 gg(DM/128, M/128);   // (8, 32)  fast path (V, O)
    dim3 g2(DM/64,  M/128);   // (16, 32) two-level path (Q, K)
    sgemm_bias_2lvl<<<g2, 256>>>(x, Wq, bq, Qp, M, DM, DM);
    sgemm_bias_2lvl<<<g2, 256>>>(x, Wk, bk, Kp, M, DM, DM);
    sgemm_bias<<<gg, 256>>>(x, Wv, bv, Vp, M, DM, DM);

    size_t smem = (size_t)QB*SEQ*4 + (size_t)QB*MAXK*4*2;  // 81920 B
    cudaFuncSetAttribute(attn_kernel, cudaFuncAttributeMaxDynamicSharedMemorySize, (int)smem);
    attn_kernel<<<dim3(SEQ/QB, BATCH*NH), 256, smem>>>(Qp, Kp, Vp, Cp);

    sgemm_bias<<<gg, 256>>>(Cp, Wo, bo, out, M, DM, DM);
}

// round 7
// speedup vs baseline: 4.7763x; 4.0019x over previous
#include <cuda_runtime.h>
#include <math.h>

#define BATCH 2
#define SEQ   2048
#define DM    1024
#define NH    16
#define HD    64
#define UTOP  38
#define QB    8

// Scratch (allocation-free rule: __device__ globals)
// Q/K/V stored head-major: [B*H][SEQ][HD]
__device__ float g_Q[BATCH*NH*SEQ*HD];
__device__ float g_K[BATCH*NH*SEQ*HD];
__device__ float g_V[BATCH*NH*SEQ*HD];
__device__ float g_S[(size_t)BATCH*NH*SEQ*SEQ];   // 536 MB score matrix
__device__ float g_C[BATCH*SEQ*DM];               // context, [B][L][DM]

// ---------------------------------------------------------------------------
// helpers: order-preserving float<->uint map
// ---------------------------------------------------------------------------
__device__ __forceinline__ unsigned f2u(float f) {
    unsigned u = __float_as_uint(f);
    return (u & 0x80000000u) ? ~u : (u | 0x80000000u);
}
__device__ __forceinline__ float u2f(unsigned m) {
    return __uint_as_float((m & 0x80000000u) ? (m & 0x7FFFFFFFu) : ~m);
}

// head-major destination index for row m (= b*SEQ+q of x) and col n (= h*HD+d)
__device__ __forceinline__ size_t hm_dest(int m, int n) {
    int b = m >> 11, q = m & (SEQ-1);
    int h = n >> 6,  d = n & (HD-1);
    return ((size_t)b << 21) + ((size_t)h << 17) + ((size_t)q << 6) + d;
}

// ---------------------------------------------------------------------------
// Fast fp32 GEMM: C[M,N] = alpha*(A[M,K] @ W[N,K]^T) + bias[N]
// 128x128 tile, BK=16, 256 threads, 8x8 register tile, double-buffered smem
// (register prefetch, one __syncthreads per k-tile).
// ---------------------------------------------------------------------------
__global__ __launch_bounds__(256) void gemm_fast(
    const float* __restrict__ A, int lda, size_t sA,
    const float* __restrict__ W, int ldw, size_t sW,
    const float* __restrict__ bias,
    float* __restrict__ Cout, int ldc, size_t sC,
    int Kdim, float alpha, int headmajor)
{
    A    += (size_t)blockIdx.z * sA;
    W    += (size_t)blockIdx.z * sW;
    Cout += (size_t)blockIdx.z * sC;

    __shared__ float As[2][16][128];
    __shared__ float Ws[2][16][128];
    int t  = threadIdx.x;
    int m0 = blockIdx.y * 128;
    int n0 = blockIdx.x * 128;
    int tm = t >> 4, tn = t & 15;
    int lr = t >> 2;          // 0..63
    int lc = (t & 3) << 2;    // 0,4,8,12

    float acc[8][8];
    #pragma unroll
    for (int i = 0; i < 8; i++)
        #pragma unroll
        for (int j = 0; j < 8; j++) acc[i][j] = 0.f;

    float4 a0, a1, w0, w1;
    a0 = *(const float4*)(A + (size_t)(m0+lr   )*lda + lc);
    a1 = *(const float4*)(A + (size_t)(m0+lr+64)*lda + lc);
    w0 = *(const float4*)(W + (size_t)(n0+lr   )*ldw + lc);
    w1 = *(const float4*)(W + (size_t)(n0+lr+64)*ldw + lc);
    As[0][lc+0][lr]    = a0.x; As[0][lc+1][lr]    = a0.y; As[0][lc+2][lr]    = a0.z; As[0][lc+3][lr]    = a0.w;
    As[0][lc+0][lr+64] = a1.x; As[0][lc+1][lr+64] = a1.y; As[0][lc+2][lr+64] = a1.z; As[0][lc+3][lr+64] = a1.w;
    Ws[0][lc+0][lr]    = w0.x; Ws[0][lc+1][lr]    = w0.y; Ws[0][lc+2][lr]    = w0.z; Ws[0][lc+3][lr]    = w0.w;
    Ws[0][lc+0][lr+64] = w1.x; Ws[0][lc+1][lr+64] = w1.y; Ws[0][lc+2][lr+64] = w1.z; Ws[0][lc+3][lr+64] = w1.w;
    __syncthreads();

    int nt = Kdim >> 4;
    for (int it = 0; it < nt; it++) {
        int cur = it & 1;
        if (it + 1 < nt) {
            int k0 = (it + 1) << 4;
            a0 = *(const float4*)(A + (size_t)(m0+lr   )*lda + k0 + lc);
            a1 = *(const float4*)(A + (size_t)(m0+lr+64)*lda + k0 + lc);
            w0 = *(const float4*)(W + (size_t)(n0+lr   )*ldw + k0 + lc);
            w1 = *(const float4*)(W + (size_t)(n0+lr+64)*ldw + k0 + lc);
        }
        #pragma unroll
        for (int kk = 0; kk < 16; kk++) {
            float a[8], bb[8];
            *(float4*)(a)    = *(const float4*)&As[cur][kk][tm*8];
            *(float4*)(a+4)  = *(const float4*)&As[cur][kk][tm*8+4];
            *(float4*)(bb)   = *(const float4*)&Ws[cur][kk][tn*8];
            *(float4*)(bb+4) = *(const float4*)&Ws[cur][kk][tn*8+4];
            #pragma unroll
            for (int i = 0; i < 8; i++)
                #pragma unroll
                for (int j = 0; j < 8; j++)
                    acc[i][j] = fmaf(a[i], bb[j], acc[i][j]);
        }
        if (it + 1 < nt) {
            int nx = (it + 1) & 1;
            As[nx][lc+0][lr]    = a0.x; As[nx][lc+1][lr]    = a0.y; As[nx][lc+2][lr]    = a0.z; As[nx][lc+3][lr]    = a0.w;
            As[nx][lc+0][lr+64] = a1.x; As[nx][lc+1][lr+64] = a1.y; As[nx][lc+2][lr+64] = a1.z; As[nx][lc+3][lr+64] = a1.w;
            Ws[nx][lc+0][lr]    = w0.x; Ws[nx][lc+1][lr]    = w0.y; Ws[nx][lc+2][lr]    = w0.z; Ws[nx][lc+3][lr]    = w0.w;
            Ws[nx][lc+0][lr+64] = w1.x; Ws[nx][lc+1][lr+64] = w1.y; Ws[nx][lc+2][lr+64] = w1.z; Ws[nx][lc+3][lr+64] = w1.w;
            __syncthreads();
        }
    }
    #pragma unroll
    for (int i = 0; i < 8; i++) {
        int m = m0 + tm*8 + i;
        #pragma unroll
        for (int j = 0; j < 8; j += 4) {
            int n = n0 + tn*8 + j;
            float4 r;
            r.x = alpha*acc[i][j]   + (bias ? bias[n+0] : 0.f);
            r.y = alpha*acc[i][j+1] + (bias ? bias[n+1] : 0.f);
            r.z = alpha*acc[i][j+2] + (bias ? bias[n+2] : 0.f);
            r.w = alpha*acc[i][j+3] + (bias ? bias[n+3] : 0.f);
            float* dst = headmajor ? (Cout + hm_dest(m, n))
                                   : (Cout + (size_t)m*ldc + n);
            *(float4*)dst = r;
        }
    }
}

// ---------------------------------------------------------------------------
// High-accuracy two-level (Kahan) GEMM. Inner: plain FMA over one BK=16 tile
// into tmp; outer: Kahan-compensated add into master accumulator. Same
// per-thread numeric sequence as the round-6 passing version.
// 128x64 tile, BK=16, 256 threads, 8x4 register tile, double-buffered.
// Used for Q/K projections and the Q.K^T score GEMM.
// ---------------------------------------------------------------------------
__global__ __launch_bounds__(256) void gemm_2lvl(
    const float* __restrict__ A, int lda, size_t sA,
    const float* __restrict__ W, int ldw, size_t sW,
    const float* __restrict__ bias,
    float* __restrict__ Cout, int ldc, size_t sC,
    int Kdim, float alpha, int headmajor)
{
    A    += (size_t)blockIdx.z * sA;
    W    += (size_t)blockIdx.z * sW;
    Cout += (size_t)blockIdx.z * sC;

    __shared__ float As[2][16][128];
    __shared__ float Ws[2][16][64];
    int t  = threadIdx.x;
    int m0 = blockIdx.y * 128;
    int n0 = blockIdx.x * 64;
    int tm = t >> 4, tn = t & 15;
    int lr = t >> 2;          // 0..63
    int lc = (t & 3) << 2;    // 0,4,8,12

    float acc[8][4], cmp[8][4];
    #pragma unroll
    for (int i = 0; i < 8; i++)
        #pragma unroll
        for (int j = 0; j < 4; j++) { acc[i][j] = 0.f; cmp[i][j] = 0.f; }

    float4 a0, a1, w0;
    a0 = *(const float4*)(A + (size_t)(m0+lr   )*lda + lc);
    a1 = *(const float4*)(A + (size_t)(m0+lr+64)*lda + lc);
    w0 = *(const float4*)(W + (size_t)(n0+lr   )*ldw + lc);
    As[0][lc+0][lr]    = a0.x; As[0][lc+1][lr]    = a0.y; As[0][lc+2][lr]    = a0.z; As[0][lc+3][lr]    = a0.w;
    As[0][lc+0][lr+64] = a1.x; As[0][lc+1][lr+64] = a1.y; As[0][lc+2][lr+64] = a1.z; As[0][lc+3][lr+64] = a1.w;
    Ws[0][lc+0][lr]    = w0.x; Ws[0][lc+1][lr]    = w0.y; Ws[0][lc+2][lr]    = w0.z; Ws[0][lc+3][lr]    = w0.w;
    __syncthreads();

    int nt = Kdim >> 4;
    for (int it = 0; it < nt; it++) {
        int cur = it & 1;
        if (it + 1 < nt) {
            int k0 = (it + 1) << 4;
            a0 = *(const float4*)(A + (size_t)(m0+lr   )*lda + k0 + lc);
            a1 = *(const float4*)(A + (size_t)(m0+lr+64)*lda + k0 + lc);
            w0 = *(const float4*)(W + (size_t)(n0+lr   )*ldw + k0 + lc);
        }

        float tmp[8][4];
        #pragma unroll
        for (int i = 0; i < 8; i++)
            #pragma unroll
            for (int j = 0; j < 4; j++) tmp[i][j] = 0.f;

        #pragma unroll
        for (int kk = 0; kk < 16; kk++) {
            float a[8], bb[4];
            *(float4*)(a)    = *(const float4*)&As[cur][kk][tm*8];
            *(float4*)(a+4)  = *(const float4*)&As[cur][kk][tm*8+4];
            *(float4*)(bb)   = *(const float4*)&Ws[cur][kk][tn*4];
            #pragma unroll
            for (int i = 0; i < 8; i++)
                #pragma unroll
                for (int j = 0; j < 4; j++)
                    tmp[i][j] = fmaf(a[i], bb[j], tmp[i][j]);
        }
        // Kahan add of tile partial into master accumulator
        #pragma unroll
        for (int i = 0; i < 8; i++)
            #pragma unroll
            for (int j = 0; j < 4; j++) {
                float y = tmp[i][j] - cmp[i][j];
                float s = acc[i][j] + y;
                cmp[i][j] = (s - acc[i][j]) - y;
                acc[i][j] = s;
            }

        if (it + 1 < nt) {
            int nx = (it + 1) & 1;
            As[nx][lc+0][lr]    = a0.x; As[nx][lc+1][lr]    = a0.y; As[nx][lc+2][lr]    = a0.z; As[nx][lc+3][lr]    = a0.w;
            As[nx][lc+0][lr+64] = a1.x; As[nx][lc+1][lr+64] = a1.y; As[nx][lc+2][lr+64] = a1.z; As[nx][lc+3][lr+64] = a1.w;
            Ws[nx][lc+0][lr]    = w0.x; Ws[nx][lc+1][lr]    = w0.y; Ws[nx][lc+2][lr]    = w0.z; Ws[nx][lc+3][lr]    = w0.w;
            __syncthreads();
        }
    }
    #pragma unroll
    for (int i = 0; i < 8; i++) {
        int m = m0 + tm*8 + i;
        int n = n0 + tn*4;
        float4 r;
        r.x = alpha*acc[i][0] + (bias ? bias[n+0] : 0.f);
        r.y = alpha*acc[i][1] + (bias ? bias[n+1] : 0.f);
        r.z = alpha*acc[i][2] + (bias ? bias[n+2] : 0.f);
        r.w = alpha*acc[i][3] + (bias ? bias[n+3] : 0.f);
        float* dst = headmajor ? (Cout + hm_dest(m, n))
                               : (Cout + (size_t)m*ldc + n);
        *(float4*)dst = r;
    }
}

// ---------------------------------------------------------------------------
// Select kernel: one warp per query row. Loads the precomputed 2048-score row
// into 64 registers (as order-preserving uints), binary-searches the exact
// fp32 38th-largest on registers (no smem), then softmax + sparse context via
// ballot + shuffle broadcast (handles ties / any count, no cap).
// Register j of lane holds k = 128*(j/4) + 4*lane + (j%4).
// ---------------------------------------------------------------------------
__global__ __launch_bounds__(256) void select_kernel(
    const float* __restrict__ S, const float* __restrict__ V,
    float* __restrict__ C)
{
    int t    = threadIdx.x;
    int qq   = t >> 5;
    int lane = t & 31;
    int bh   = blockIdx.y;
    int b    = bh >> 4, h = bh & 15;
    int q    = blockIdx.x * QB + qq;

    const float4* Srow = (const float4*)(S + ((size_t)bh*SEQ + q)*SEQ);

    unsigned u[64];
    unsigned umax = 0u;
    #pragma unroll
    for (int i = 0; i < 16; i++) {
        float4 v = Srow[i*32 + lane];
        unsigned u0 = f2u(v.x), u1 = f2u(v.y), u2 = f2u(v.z), u3 = f2u(v.w);
        u[4*i+0] = u0; u[4*i+1] = u1; u[4*i+2] = u2; u[4*i+3] = u3;
        umax = max(umax, max(max(u0,u1), max(u2,u3)));
    }
    #pragma unroll
    for (int o = 16; o; o >>= 1)
        umax = max(umax, __shfl_xor_sync(0xffffffffu, umax, o));

    // Exact fp32 U-th largest via binary search on registers.
    unsigned lo = 0u, hi = umax;
    while (lo < hi) {
        unsigned d   = hi - lo;
        unsigned mid = lo + (d >> 1) + (d & 1u);   // ceil midpoint
        int c = 0;
        #pragma unroll
        for (int j = 0; j < 64; j++) c += (u[j] >= mid) ? 1 : 0;
        #pragma unroll
        for (int o = 16; o; o >>= 1) c += __shfl_xor_sync(0xffffffffu, c, o);
        if (c >= UTOP) lo = mid; else hi = mid - 1;
    }
    const unsigned uth = lo;
    const float mymax = u2f(umax);

    // softmax + sparse context (ballot + shuffle broadcast)
    const float* Vb = V + ((size_t)bh*SEQ)*HD;
    float sum = 0.f, acc0 = 0.f, acc1 = 0.f;
    #pragma unroll
    for (int j = 0; j < 64; j++) {
        bool keep = (u[j] >= uth);
        float p = keep ? __expf(u2f(u[j]) - mymax) : 0.f;
        sum += p;
        unsigned msk = __ballot_sync(0xffffffffu, keep);
        int kb = ((j >> 2) << 7) + (j & 3);
        while (msk) {
            int src = __ffs(msk) - 1; msk &= msk - 1;
            float pb = __shfl_sync(0xffffffffu, p, src);
            const float* vr = Vb + (size_t)(kb + (src << 2))*HD;
            acc0 = fmaf(pb, vr[lane],      acc0);
            acc1 = fmaf(pb, vr[lane + 32], acc1);
        }
    }
    #pragma unroll
    for (int o = 16; o; o >>= 1) sum += __shfl_xor_sync(0xffffffffu, sum, o);
    float inv = 1.f / sum;

    float* out = C + ((size_t)(b*SEQ + q))*DM + h*HD;
    out[lane]      = acc0 * inv;
    out[lane + 32] = acc1 * inv;
}

// ---------------------------------------------------------------------------
extern "C" void kernel_launch(void* const* d_in, const int* in_sizes, int n_in,
                              void* d_out, int out_size)
{
    const float* x  = (const float*)d_in[0];
    const float* Wq = (const float*)d_in[1];
    const float* bq = (const float*)d_in[2];
    const float* Wk = (const float*)d_in[3];
    const float* bk = (const float*)d_in[4];
    const float* Wv = (const float*)d_in[5];
    const float* bv = (const float*)d_in[6];
    const float* Wo = (const float*)d_in[7];
    const float* bo = (const float*)d_in[8];
    float* out = (float*)d_out;

    float *Qp, *Kp, *Vp, *Sp, *Cp;
    cudaGetSymbolAddress((void**)&Qp, g_Q);
    cudaGetSymbolAddress((void**)&Kp, g_K);
    cudaGetSymbolAddress((void**)&Vp, g_V);
    cudaGetSymbolAddress((void**)&Sp, g_S);
    cudaGetSymbolAddress((void**)&Cp, g_C);

    const int M = BATCH * SEQ;   // 4096

    // Q, K projections (high accuracy, head-major out)
    gemm_2lvl<<<dim3(DM/64, M/128, 1), 256>>>(x, DM, 0, Wq, DM, 0, bq,
                                              Qp, 0, 0, DM, 1.f, 1);
    gemm_2lvl<<<dim3(DM/64, M/128, 1), 256>>>(x, DM, 0, Wk, DM, 0, bk,
                                              Kp, 0, 0, DM, 1.f, 1);
    // V projection (fast, head-major out)
    gemm_fast<<<dim3(DM/128, M/128, 1), 256>>>(x, DM, 0, Wv, DM, 0, bv,
                                               Vp, 0, 0, DM, 1.f, 1);

    // Scores: S[bh] = 0.125 * Q[bh] @ K[bh]^T   (high accuracy)
    gemm_2lvl<<<dim3(SEQ/64, SEQ/128, BATCH*NH), 256>>>(
        Qp, HD, (size_t)SEQ*HD, Kp, HD, (size_t)SEQ*HD, (const float*)0,
        Sp, SEQ, (size_t)SEQ*SEQ, HD, 0.125f, 0);

    // Top-38 select + softmax + sparse AV
    select_kernel<<<dim3(SEQ/QB, BATCH*NH), 256>>>(Sp, Vp, Cp);

    // Output projection
    gemm_fast<<<dim3(DM/128, M/128, 1), 256>>>(Cp, DM, 0, Wo, DM, 0, bo,
                                               out, DM, 0, DM, 1.f, 0);
}

// round 8
// speedup vs baseline: 4.9101x; 1.0280x over previous
#include <cuda_runtime.h>
#include <math.h>

#define BATCH 2
#define SEQ   2048
#define DM    1024
#define NH    16
#define HD    64
#define UTOP  38
#define QB    8

// Scratch (allocation-free rule: __device__ globals)
// Q/K/V stored head-major: [B*H][SEQ][HD]
__device__ float g_Q[BATCH*NH*SEQ*HD];
__device__ float g_K[BATCH*NH*SEQ*HD];
__device__ float g_V[BATCH*NH*SEQ*HD];
__device__ float g_S[(size_t)BATCH*NH*SEQ*SEQ];   // 536 MB score matrix
__device__ float g_C[BATCH*SEQ*DM];               // context, [B][L][DM]

// ---------------------------------------------------------------------------
// helpers: order-preserving float<->uint map
// ---------------------------------------------------------------------------
__device__ __forceinline__ unsigned f2u(float f) {
    unsigned u = __float_as_uint(f);
    return (u & 0x80000000u) ? ~u : (u | 0x80000000u);
}
__device__ __forceinline__ float u2f(unsigned m) {
    return __uint_as_float((m & 0x80000000u) ? (m & 0x7FFFFFFFu) : ~m);
}

// head-major destination index for row m (= b*SEQ+q of x) and col n (= h*HD+d)
__device__ __forceinline__ size_t hm_dest(int m, int n) {
    int b = m >> 11, q = m & (SEQ-1);
    int h = n >> 6,  d = n & (HD-1);
    return ((size_t)b << 21) + ((size_t)h << 17) + ((size_t)q << 6) + d;
}

// ---------------------------------------------------------------------------
// Fast fp32 GEMM: C[M,N] = alpha*(A[M,K] @ W[N,K]^T) + bias[N]
// 128x128 tile, BK=16, 256 threads, 8x8 register tile, double-buffered smem.
// ---------------------------------------------------------------------------
__global__ __launch_bounds__(256) void gemm_fast(
    const float* __restrict__ A, int lda, size_t sA,
    const float* __restrict__ W, int ldw, size_t sW,
    const float* __restrict__ bias,
    float* __restrict__ Cout, int ldc, size_t sC,
    int Kdim, float alpha, int headmajor)
{
    A    += (size_t)blockIdx.z * sA;
    W    += (size_t)blockIdx.z * sW;
    Cout += (size_t)blockIdx.z * sC;

    __shared__ float As[2][16][128];
    __shared__ float Ws[2][16][128];
    int t  = threadIdx.x;
    int m0 = blockIdx.y * 128;
    int n0 = blockIdx.x * 128;
    int tm = t >> 4, tn = t & 15;
    int lr = t >> 2;          // 0..63
    int lc = (t & 3) << 2;    // 0,4,8,12

    float acc[8][8];
    #pragma unroll
    for (int i = 0; i < 8; i++)
        #pragma unroll
        for (int j = 0; j < 8; j++) acc[i][j] = 0.f;

    float4 a0, a1, w0, w1;
    a0 = *(const float4*)(A + (size_t)(m0+lr   )*lda + lc);
    a1 = *(const float4*)(A + (size_t)(m0+lr+64)*lda + lc);
    w0 = *(const float4*)(W + (size_t)(n0+lr   )*ldw + lc);
    w1 = *(const float4*)(W + (size_t)(n0+lr+64)*ldw + lc);
    As[0][lc+0][lr]    = a0.x; As[0][lc+1][lr]    = a0.y; As[0][lc+2][lr]    = a0.z; As[0][lc+3][lr]    = a0.w;
    As[0][lc+0][lr+64] = a1.x; As[0][lc+1][lr+64] = a1.y; As[0][lc+2][lr+64] = a1.z; As[0][lc+3][lr+64] = a1.w;
    Ws[0][lc+0][lr]    = w0.x; Ws[0][lc+1][lr]    = w0.y; Ws[0][lc+2][lr]    = w0.z; Ws[0][lc+3][lr]    = w0.w;
    Ws[0][lc+0][lr+64] = w1.x; Ws[0][lc+1][lr+64] = w1.y; Ws[0][lc+2][lr+64] = w1.z; Ws[0][lc+3][lr+64] = w1.w;
    __syncthreads();

    int nt = Kdim >> 4;
    for (int it = 0; it < nt; it++) {
        int cur = it & 1;
        if (it + 1 < nt) {
            int k0 = (it + 1) << 4;
            a0 = *(const float4*)(A + (size_t)(m0+lr   )*lda + k0 + lc);
            a1 = *(const float4*)(A + (size_t)(m0+lr+64)*lda + k0 + lc);
            w0 = *(const float4*)(W + (size_t)(n0+lr   )*ldw + k0 + lc);
            w1 = *(const float4*)(W + (size_t)(n0+lr+64)*ldw + k0 + lc);
        }
        #pragma unroll
        for (int kk = 0; kk < 16; kk++) {
            float a[8], bb[8];
            *(float4*)(a)    = *(const float4*)&As[cur][kk][tm*8];
            *(float4*)(a+4)  = *(const float4*)&As[cur][kk][tm*8+4];
            *(float4*)(bb)   = *(const float4*)&Ws[cur][kk][tn*8];
            *(float4*)(bb+4) = *(const float4*)&Ws[cur][kk][tn*8+4];
            #pragma unroll
            for (int i = 0; i < 8; i++)
                #pragma unroll
                for (int j = 0; j < 8; j++)
                    acc[i][j] = fmaf(a[i], bb[j], acc[i][j]);
        }
        if (it + 1 < nt) {
            int nx = (it + 1) & 1;
            As[nx][lc+0][lr]    = a0.x; As[nx][lc+1][lr]    = a0.y; As[nx][lc+2][lr]    = a0.z; As[nx][lc+3][lr]    = a0.w;
            As[nx][lc+0][lr+64] = a1.x; As[nx][lc+1][lr+64] = a1.y; As[nx][lc+2][lr+64] = a1.z; As[nx][lc+3][lr+64] = a1.w;
            Ws[nx][lc+0][lr]    = w0.x; Ws[nx][lc+1][lr]    = w0.y; Ws[nx][lc+2][lr]    = w0.z; Ws[nx][lc+3][lr]    = w0.w;
            Ws[nx][lc+0][lr+64] = w1.x; Ws[nx][lc+1][lr+64] = w1.y; Ws[nx][lc+2][lr+64] = w1.z; Ws[nx][lc+3][lr+64] = w1.w;
            __syncthreads();
        }
    }
    #pragma unroll
    for (int i = 0; i < 8; i++) {
        int m = m0 + tm*8 + i;
        #pragma unroll
        for (int j = 0; j < 8; j += 4) {
            int n = n0 + tn*8 + j;
            float4 r;
            r.x = alpha*acc[i][j]   + (bias ? bias[n+0] : 0.f);
            r.y = alpha*acc[i][j+1] + (bias ? bias[n+1] : 0.f);
            r.z = alpha*acc[i][j+2] + (bias ? bias[n+2] : 0.f);
            r.w = alpha*acc[i][j+3] + (bias ? bias[n+3] : 0.f);
            float* dst = headmajor ? (Cout + hm_dest(m, n))
                                   : (Cout + (size_t)m*ldc + n);
            *(float4*)dst = r;
        }
    }
}

// ---------------------------------------------------------------------------
// Mid-accuracy GEMM for the score matmul: 2-level PLAIN accumulation
// (BK=16 tmp chain + plain outer add across k-tiles). For K=64 this gives
// chains of 16 + outer chain of 4 — strictly tighter than the round-6
// passing split-2 scheme — without Kahan's 31% op overhead.
// 128x128 tile, 8x8 register tile, double-buffered.
// ---------------------------------------------------------------------------
__global__ __launch_bounds__(256) void gemm_mid(
    const float* __restrict__ A, int lda, size_t sA,
    const float* __restrict__ W, int ldw, size_t sW,
    float* __restrict__ Cout, int ldc, size_t sC,
    int Kdim, float alpha)
{
    A    += (size_t)blockIdx.z * sA;
    W    += (size_t)blockIdx.z * sW;
    Cout += (size_t)blockIdx.z * sC;

    __shared__ float As[2][16][128];
    __shared__ float Ws[2][16][128];
    int t  = threadIdx.x;
    int m0 = blockIdx.y * 128;
    int n0 = blockIdx.x * 128;
    int tm = t >> 4, tn = t & 15;
    int lr = t >> 2;
    int lc = (t & 3) << 2;

    float acc[8][8];
    #pragma unroll
    for (int i = 0; i < 8; i++)
        #pragma unroll
        for (int j = 0; j < 8; j++) acc[i][j] = 0.f;

    float4 a0, a1, w0, w1;
    a0 = *(const float4*)(A + (size_t)(m0+lr   )*lda + lc);
    a1 = *(const float4*)(A + (size_t)(m0+lr+64)*lda + lc);
    w0 = *(const float4*)(W + (size_t)(n0+lr   )*ldw + lc);
    w1 = *(const float4*)(W + (size_t)(n0+lr+64)*ldw + lc);
    As[0][lc+0][lr]    = a0.x; As[0][lc+1][lr]    = a0.y; As[0][lc+2][lr]    = a0.z; As[0][lc+3][lr]    = a0.w;
    As[0][lc+0][lr+64] = a1.x; As[0][lc+1][lr+64] = a1.y; As[0][lc+2][lr+64] = a1.z; As[0][lc+3][lr+64] = a1.w;
    Ws[0][lc+0][lr]    = w0.x; Ws[0][lc+1][lr]    = w0.y; Ws[0][lc+2][lr]    = w0.z; Ws[0][lc+3][lr]    = w0.w;
    Ws[0][lc+0][lr+64] = w1.x; Ws[0][lc+1][lr+64] = w1.y; Ws[0][lc+2][lr+64] = w1.z; Ws[0][lc+3][lr+64] = w1.w;
    __syncthreads();

    int nt = Kdim >> 4;
    for (int it = 0; it < nt; it++) {
        int cur = it & 1;
        if (it + 1 < nt) {
            int k0 = (it + 1) << 4;
            a0 = *(const float4*)(A + (size_t)(m0+lr   )*lda + k0 + lc);
            a1 = *(const float4*)(A + (size_t)(m0+lr+64)*lda + k0 + lc);
            w0 = *(const float4*)(W + (size_t)(n0+lr   )*ldw + k0 + lc);
            w1 = *(const float4*)(W + (size_t)(n0+lr+64)*ldw + k0 + lc);
        }
        float tmpr[8][8];
        #pragma unroll
        for (int i = 0; i < 8; i++)
            #pragma unroll
            for (int j = 0; j < 8; j++) tmpr[i][j] = 0.f;

        #pragma unroll
        for (int kk = 0; kk < 16; kk++) {
            float a[8], bb[8];
            *(float4*)(a)    = *(const float4*)&As[cur][kk][tm*8];
            *(float4*)(a+4)  = *(const float4*)&As[cur][kk][tm*8+4];
            *(float4*)(bb)   = *(const float4*)&Ws[cur][kk][tn*8];
            *(float4*)(bb+4) = *(const float4*)&Ws[cur][kk][tn*8+4];
            #pragma unroll
            for (int i = 0; i < 8; i++)
                #pragma unroll
                for (int j = 0; j < 8; j++)
                    tmpr[i][j] = fmaf(a[i], bb[j], tmpr[i][j]);
        }
        #pragma unroll
        for (int i = 0; i < 8; i++)
            #pragma unroll
            for (int j = 0; j < 8; j++) acc[i][j] += tmpr[i][j];

        if (it + 1 < nt) {
            int nx = (it + 1) & 1;
            As[nx][lc+0][lr]    = a0.x; As[nx][lc+1][lr]    = a0.y; As[nx][lc+2][lr]    = a0.z; As[nx][lc+3][lr]    = a0.w;
            As[nx][lc+0][lr+64] = a1.x; As[nx][lc+1][lr+64] = a1.y; As[nx][lc+2][lr+64] = a1.z; As[nx][lc+3][lr+64] = a1.w;
            Ws[nx][lc+0][lr]    = w0.x; Ws[nx][lc+1][lr]    = w0.y; Ws[nx][lc+2][lr]    = w0.z; Ws[nx][lc+3][lr]    = w0.w;
            Ws[nx][lc+0][lr+64] = w1.x; Ws[nx][lc+1][lr+64] = w1.y; Ws[nx][lc+2][lr+64] = w1.z; Ws[nx][lc+3][lr+64] = w1.w;
            __syncthreads();
        }
    }
    #pragma unroll
    for (int i = 0; i < 8; i++) {
        int m = m0 + tm*8 + i;
        #pragma unroll
        for (int j = 0; j < 8; j += 4) {
            int n = n0 + tn*8 + j;
            float4 r;
            r.x = alpha*acc[i][j];
            r.y = alpha*acc[i][j+1];
            r.z = alpha*acc[i][j+2];
            r.w = alpha*acc[i][j+3];
            *(float4*)(Cout + (size_t)m*ldc + n) = r;
        }
    }
}

// ---------------------------------------------------------------------------
// High-accuracy two-level (Kahan) GEMM — Q/K projections only.
// 128x64 tile, BK=16, 256 threads, 8x4 register tile, double-buffered.
// (Numerically identical to the round-6/7 passing version.)
// ---------------------------------------------------------------------------
__global__ __launch_bounds__(256) void gemm_2lvl(
    const float* __restrict__ A, int lda, size_t sA,
    const float* __restrict__ W, int ldw, size_t sW,
    const float* __restrict__ bias,
    float* __restrict__ Cout, int ldc, size_t sC,
    int Kdim, float alpha, int headmajor)
{
    A    += (size_t)blockIdx.z * sA;
    W    += (size_t)blockIdx.z * sW;
    Cout += (size_t)blockIdx.z * sC;

    __shared__ float As[2][16][128];
    __shared__ float Ws[2][16][64];
    int t  = threadIdx.x;
    int m0 = blockIdx.y * 128;
    int n0 = blockIdx.x * 64;
    int tm = t >> 4, tn = t & 15;
    int lr = t >> 2;
    int lc = (t & 3) << 2;

    float acc[8][4], cmp[8][4];
    #pragma unroll
    for (int i = 0; i < 8; i++)
        #pragma unroll
        for (int j = 0; j < 4; j++) { acc[i][j] = 0.f; cmp[i][j] = 0.f; }

    float4 a0, a1, w0;
    a0 = *(const float4*)(A + (size_t)(m0+lr   )*lda + lc);
    a1 = *(const float4*)(A + (size_t)(m0+lr+64)*lda + lc);
    w0 = *(const float4*)(W + (size_t)(n0+lr   )*ldw + lc);
    As[0][lc+0][lr]    = a0.x; As[0][lc+1][lr]    = a0.y; As[0][lc+2][lr]    = a0.z; As[0][lc+3][lr]    = a0.w;
    As[0][lc+0][lr+64] = a1.x; As[0][lc+1][lr+64] = a1.y; As[0][lc+2][lr+64] = a1.z; As[0][lc+3][lr+64] = a1.w;
    Ws[0][lc+0][lr]    = w0.x; Ws[0][lc+1][lr]    = w0.y; Ws[0][lc+2][lr]    = w0.z; Ws[0][lc+3][lr]    = w0.w;
    __syncthreads();

    int nt = Kdim >> 4;
    for (int it = 0; it < nt; it++) {
        int cur = it & 1;
        if (it + 1 < nt) {
            int k0 = (it + 1) << 4;
            a0 = *(const float4*)(A + (size_t)(m0+lr   )*lda + k0 + lc);
            a1 = *(const float4*)(A + (size_t)(m0+lr+64)*lda + k0 + lc);
            w0 = *(const float4*)(W + (size_t)(n0+lr   )*ldw + k0 + lc);
        }

        float tmp[8][4];
        #pragma unroll
        for (int i = 0; i < 8; i++)
            #pragma unroll
            for (int j = 0; j < 4; j++) tmp[i][j] = 0.f;

        #pragma unroll
        for (int kk = 0; kk < 16; kk++) {
            float a[8], bb[4];
            *(float4*)(a)    = *(const float4*)&As[cur][kk][tm*8];
            *(float4*)(a+4)  = *(const float4*)&As[cur][kk][tm*8+4];
            *(float4*)(bb)   = *(const float4*)&Ws[cur][kk][tn*4];
            #pragma unroll
            for (int i = 0; i < 8; i++)
                #pragma unroll
                for (int j = 0; j < 4; j++)
                    tmp[i][j] = fmaf(a[i], bb[j], tmp[i][j]);
        }
        #pragma unroll
        for (int i = 0; i < 8; i++)
            #pragma unroll
            for (int j = 0; j < 4; j++) {
                float y = tmp[i][j] - cmp[i][j];
                float s = acc[i][j] + y;
                cmp[i][j] = (s - acc[i][j]) - y;
                acc[i][j] = s;
            }

        if (it + 1 < nt) {
            int nx = (it + 1) & 1;
            As[nx][lc+0][lr]    = a0.x; As[nx][lc+1][lr]    = a0.y; As[nx][lc+2][lr]    = a0.z; As[nx][lc+3][lr]    = a0.w;
            As[nx][lc+0][lr+64] = a1.x; As[nx][lc+1][lr+64] = a1.y; As[nx][lc+2][lr+64] = a1.z; As[nx][lc+3][lr+64] = a1.w;
            Ws[nx][lc+0][lr]    = w0.x; Ws[nx][lc+1][lr]    = w0.y; Ws[nx][lc+2][lr]    = w0.z; Ws[nx][lc+3][lr]    = w0.w;
            __syncthreads();
        }
    }
    #pragma unroll
    for (int i = 0; i < 8; i++) {
        int m = m0 + tm*8 + i;
        int n = n0 + tn*4;
        float4 r;
        r.x = alpha*acc[i][0] + (bias ? bias[n+0] : 0.f);
        r.y = alpha*acc[i][1] + (bias ? bias[n+1] : 0.f);
        r.z = alpha*acc[i][2] + (bias ? bias[n+2] : 0.f);
        r.w = alpha*acc[i][3] + (bias ? bias[n+3] : 0.f);
        float* dst = headmajor ? (Cout + hm_dest(m, n))
                               : (Cout + (size_t)m*ldc + n);
        *(float4*)dst = r;
    }
}

// ---------------------------------------------------------------------------
// Select kernel v2: one warp per query row, scores in 64 regs.
// Fast path: per-lane sorted top-6 -> 38th of the 192 candidates via binary
// search -> exact validation against all 2048 values (count(>=t) >= 38 AND
// count(>t) < 38  <=>  t is exactly the 38th-largest). Fallback (~0.5% of
// rows): full binary search. Then softmax + ballot/shuffle sparse AV.
// ---------------------------------------------------------------------------
__global__ __launch_bounds__(256) void select_kernel(
    const float* __restrict__ S, const float* __restrict__ V,
    float* __restrict__ C)
{
    int t    = threadIdx.x;
    int qq   = t >> 5;
    int lane = t & 31;
    int bh   = blockIdx.y;
    int b    = bh >> 4, h = bh & 15;
    int q    = blockIdx.x * QB + qq;

    const float4* Srow = (const float4*)(S + ((size_t)bh*SEQ + q)*SEQ);

    unsigned u[64];
    unsigned umax = 0u;
    unsigned c0=0,c1=0,c2=0,c3=0,c4=0,c5=0;   // per-lane top-6, descending
    #pragma unroll
    for (int i = 0; i < 16; i++) {
        float4 v = Srow[i*32 + lane];
        unsigned uu[4] = { f2u(v.x), f2u(v.y), f2u(v.z), f2u(v.w) };
        #pragma unroll
        for (int s = 0; s < 4; s++) {
            unsigned w = uu[s];
            u[4*i+s] = w;
            if (w > c5) {
                c5 = w;
                if (c5 > c4) { unsigned x=c4; c4=c5; c5=x; }
                if (c4 > c3) { unsigned x=c3; c3=c4; c4=x; }
                if (c3 > c2) { unsigned x=c2; c2=c3; c3=x; }
                if (c2 > c1) { unsigned x=c1; c1=c2; c2=x; }
                if (c1 > c0) { unsigned x=c0; c0=c1; c1=x; }
            }
        }
    }
    umax = c0;
    #pragma unroll
    for (int o = 16; o; o >>= 1)
        umax = max(umax, __shfl_xor_sync(0xffffffffu, umax, o));

    // 38th among the 192 candidates (binary search over value space)
    unsigned lo = 0u, hi = umax;
    while (lo < hi) {
        unsigned d   = hi - lo;
        unsigned mid = lo + (d >> 1) + (d & 1u);
        int c = (c0>=mid) + (c1>=mid) + (c2>=mid) + (c3>=mid) + (c4>=mid) + (c5>=mid);
        #pragma unroll
        for (int o = 16; o; o >>= 1) c += __shfl_xor_sync(0xffffffffu, c, o);
        if (c >= UTOP) lo = mid; else hi = mid - 1;
    }
    unsigned uth = lo;

    // exact validation against the full row
    {
        int pack = 0;
        #pragma unroll
        for (int j = 0; j < 64; j++) {
            pack += (u[j] >= uth) ? 1 : 0;
            pack += (u[j] >  uth) ? (1 << 16) : 0;
        }
        #pragma unroll
        for (int o = 16; o; o >>= 1) pack += __shfl_xor_sync(0xffffffffu, pack, o);
        int cge = pack & 0xFFFF, cgt = pack >> 16;
        if (!(cge >= UTOP && cgt < UTOP)) {
            // fallback: exact full binary search
            lo = 0u; hi = umax;
            while (lo < hi) {
                unsigned d   = hi - lo;
                unsigned mid = lo + (d >> 1) + (d & 1u);
                int c = 0;
                #pragma unroll
                for (int j = 0; j < 64; j++) c += (u[j] >= mid) ? 1 : 0;
                #pragma unroll
                for (int o = 16; o; o >>= 1) c += __shfl_xor_sync(0xffffffffu, c, o);
                if (c >= UTOP) lo = mid; else hi = mid - 1;
            }
            uth = lo;
        }
    }
    const float mymax = u2f(umax);

    // softmax + sparse context (ballot + shuffle broadcast)
    const float* Vb = V + ((size_t)bh*SEQ)*HD;
    float sum = 0.f, acc0 = 0.f, acc1 = 0.f;
    #pragma unroll
    for (int j = 0; j < 64; j++) {
        bool keep = (u[j] >= uth);
        float p = keep ? __expf(u2f(u[j]) - mymax) : 0.f;
        sum += p;
        unsigned msk = __ballot_sync(0xffffffffu, keep);
        int kb = ((j >> 2) << 7) + (j & 3);
        while (msk) {
            int src = __ffs(msk) - 1; msk &= msk - 1;
            float pb = __shfl_sync(0xffffffffu, p, src);
            const float* vr = Vb + (size_t)(kb + (src << 2))*HD;
            acc0 = fmaf(pb, vr[lane],      acc0);
            acc1 = fmaf(pb, vr[lane + 32], acc1);
        }
    }
    #pragma unroll
    for (int o = 16; o; o >>= 1) sum += __shfl_xor_sync(0xffffffffu, sum, o);
    float inv = 1.f / sum;

    float* out = C + ((size_t)(b*SEQ + q))*DM + h*HD;
    out[lane]      = acc0 * inv;
    out[lane + 32] = acc1 * inv;
}

// ---------------------------------------------------------------------------
extern "C" void kernel_launch(void* const* d_in, const int* in_sizes, int n_in,
                              void* d_out, int out_size)
{
    const float* x  = (const float*)d_in[0];
    const float* Wq = (const float*)d_in[1];
    const float* bq = (const float*)d_in[2];
    const float* Wk = (const float*)d_in[3];
    const float* bk = (const float*)d_in[4];
    const float* Wv = (const float*)d_in[5];
    const float* bv = (const float*)d_in[6];
    const float* Wo = (const float*)d_in[7];
    const float* bo = (const float*)d_in[8];
    float* out = (float*)d_out;

    float *Qp, *Kp, *Vp, *Sp, *Cp;
    cudaGetSymbolAddress((void**)&Qp, g_Q);
    cudaGetSymbolAddress((void**)&Kp, g_K);
    cudaGetSymbolAddress((void**)&Vp, g_V);
    cudaGetSymbolAddress((void**)&Sp, g_S);
    cudaGetSymbolAddress((void**)&Cp, g_C);

    const int M = BATCH * SEQ;   // 4096

    // Q, K projections (high accuracy, head-major out)
    gemm_2lvl<<<dim3(DM/64, M/128, 1), 256>>>(x, DM, 0, Wq, DM, 0, bq,
                                              Qp, 0, 0, DM, 1.f, 1);
    gemm_2lvl<<<dim3(DM/64, M/128, 1), 256>>>(x, DM, 0, Wk, DM, 0, bk,
                                              Kp, 0, 0, DM, 1.f, 1);
    // V projection (fast, head-major out)
    gemm_fast<<<dim3(DM/128, M/128, 1), 256>>>(x, DM, 0, Wv, DM, 0, bv,
                                               Vp, 0, 0, DM, 1.f, 1);

    // Scores: S[bh] = 0.125 * Q[bh] @ K[bh]^T   (2-level plain accumulation)
    gemm_mid<<<dim3(SEQ/128, SEQ/128, BATCH*NH), 256>>>(
        Qp, HD, (size_t)SEQ*HD, Kp, HD, (size_t)SEQ*HD,
        Sp, SEQ, (size_t)SEQ*SEQ, HD, 0.125f);

    // Top-38 select + softmax + sparse AV
    select_kernel<<<dim3(SEQ/QB, BATCH*NH), 256>>>(Sp, Vp, Cp);

    // Output projection
    gemm_fast<<<dim3(DM/128, M/128, 1), 256>>>(Cp, DM, 0, Wo, DM, 0, bo,
                                               out, DM, 0, DM, 1.f, 0);
}